// round 1
// baseline (speedup 1.0000x reference)
#include <cuda_runtime.h>
#include <cuda_bf16.h>
#include <math.h>

// Problem constants
#define BATCH 8
#define LEN   2048
#define DIM   1024
#define DFF   4096
#define NFFT  4096
#define LN_EPS 1e-5f

// ---------------------------------------------------------------------------
// Static device scratch (no allocation allowed)
// ---------------------------------------------------------------------------
__device__ float  g_lnz  [BATCH * LEN * DIM];        // 64 MB : LN(z)
__device__ float  g_hfilt[LEN * DIM];                // 8  MB : ffn(pos)
__device__ float2 g_wfh  [DIM * NFFT];               // 32 MB : filter spectrum
__device__ float  g_znew [BATCH * LEN * DIM];        // 64 MB
__device__ float  g_X    [BATCH * LEN * DIM];        // 64 MB : LN(znew)
__device__ float  g_H    [BATCH * LEN * DFF];        // 256MB : FFN hidden (reused)

// ---------------------------------------------------------------------------
// FFT helpers: 4096-point complex FFT in shared memory, 256 threads/block
// ---------------------------------------------------------------------------
__device__ __forceinline__ float2 cmul(float2 a, float2 b) {
    return make_float2(a.x * b.x - a.y * b.y, a.x * b.y + a.y * b.x);
}

// SIGN = -1 : forward ; SIGN = +1 : inverse (unscaled)
template <int SIGN>
__device__ void fft4096(float2* sm, const float2* tw) {
    const int tid = threadIdx.x;  // 256 threads
    __syncthreads();
    // bit-reversal permutation (12 bits)
    for (int i = tid; i < NFFT; i += 256) {
        int r = __brev(i) >> 20;
        if (r > i) { float2 t = sm[i]; sm[i] = sm[r]; sm[r] = t; }
    }
    __syncthreads();
    for (int len = 2; len <= NFFT; len <<= 1) {
        const int half = len >> 1;
        const int step = NFFT / len;
        for (int j = tid; j < NFFT / 2; j += 256) {
            const int pos = j & (half - 1);
            const int i0  = 2 * j - pos;
            const int i1  = i0 + half;
            float2 w = tw[pos * step];
            if (SIGN > 0) w.y = -w.y;
            float2 u = sm[i0];
            float2 v = cmul(sm[i1], w);
            sm[i0] = make_float2(u.x + v.x, u.y + v.y);
            sm[i1] = make_float2(u.x - v.x, u.y - v.y);
        }
        __syncthreads();
    }
}

__device__ __forceinline__ void fill_twiddles(float2* tw) {
    for (int k = threadIdx.x; k < NFFT / 2; k += 256) {
        float s, c;
        sincosf(-6.2831853071795864769f * (float)k / (float)NFFT, &s, &c);
        tw[k] = make_float2(c, s);
    }
}

// ---------------------------------------------------------------------------
// LayerNorm over last axis (D=1024). One block per row, 256 threads.
// ---------------------------------------------------------------------------
__global__ void layernorm_rows(const float* __restrict__ x,
                               const float* __restrict__ gvec,
                               const float* __restrict__ bvec,
                               float* __restrict__ y) {
    const int row = blockIdx.x;
    const int tid = threadIdx.x;
    const float4* xr = reinterpret_cast<const float4*>(x + (size_t)row * DIM);
    float4 v = xr[tid];
    float s  = v.x + v.y + v.z + v.w;
    float s2 = v.x * v.x + v.y * v.y + v.z * v.z + v.w * v.w;
    __shared__ float rs[256], rs2[256];
    rs[tid] = s; rs2[tid] = s2;
    __syncthreads();
    for (int o = 128; o > 0; o >>= 1) {
        if (tid < o) { rs[tid] += rs[tid + o]; rs2[tid] += rs2[tid + o]; }
        __syncthreads();
    }
    const float mean = rs[0] * (1.0f / DIM);
    const float var  = rs2[0] * (1.0f / DIM) - mean * mean;
    const float rstd = rsqrtf(var + LN_EPS);
    const float4 gg = reinterpret_cast<const float4*>(gvec)[tid];
    const float4 bb = reinterpret_cast<const float4*>(bvec)[tid];
    float4 o;
    o.x = (v.x - mean) * rstd * gg.x + bb.x;
    o.y = (v.y - mean) * rstd * gg.y + bb.y;
    o.z = (v.z - mean) * rstd * gg.z + bb.z;
    o.w = (v.w - mean) * rstd * gg.w + bb.w;
    reinterpret_cast<float4*>(y + (size_t)row * DIM)[tid] = o;
}

// ---------------------------------------------------------------------------
// Filter spectrum: per channel d, FFT( window(t) * hfilt[t,d], padded to 4096 )
// ---------------------------------------------------------------------------
__global__ void filter_fft(const float* __restrict__ hfilt,
                           const float* __restrict__ a,
                           float2* __restrict__ wfh) {
    __shared__ float2 data[NFFT];
    __shared__ float2 tw[NFFT / 2];
    const int d   = blockIdx.x;
    const int tid = threadIdx.x;
    const float ea = expf(a[0]);
    for (int t = tid; t < LEN; t += 256) {
        float w = expf(-(float)t * ea);
        data[t] = make_float2(hfilt[(size_t)t * DIM + d] * w, 0.0f);
    }
    for (int t = LEN + tid; t < NFFT; t += 256) data[t] = make_float2(0.0f, 0.0f);
    fill_twiddles(tw);
    fft4096<-1>(data, tw);
    for (int k = tid; k < NFFT; k += 256) wfh[(size_t)d * NFFT + k] = data[k];
}

// ---------------------------------------------------------------------------
// FFT convolution per (batch, dim) column:
//   znew[b,t,d] = IFFT( FFT(lnz[b,:,d] pad) * WFH[d] )[t].re / N + hidden[t,d]
// ---------------------------------------------------------------------------
__global__ void fftconv(const float* __restrict__ lnz,
                        const float2* __restrict__ wfh,
                        const float* __restrict__ hidden,
                        float* __restrict__ znew) {
    __shared__ float2 data[NFFT];
    __shared__ float2 tw[NFFT / 2];
    const int col = blockIdx.x;            // b * DIM + d
    const int b   = col >> 10;
    const int d   = col & (DIM - 1);
    const int tid = threadIdx.x;
    for (int t = tid; t < LEN; t += 256)
        data[t] = make_float2(lnz[((size_t)b * LEN + t) * DIM + d], 0.0f);
    for (int t = LEN + tid; t < NFFT; t += 256) data[t] = make_float2(0.0f, 0.0f);
    fill_twiddles(tw);
    fft4096<-1>(data, tw);
    for (int k = tid; k < NFFT; k += 256)
        data[k] = cmul(data[k], wfh[(size_t)d * NFFT + k]);
    fft4096<1>(data, tw);
    const float inv = 1.0f / (float)NFFT;
    for (int t = tid; t < LEN; t += 256)
        znew[((size_t)b * LEN + t) * DIM + d] =
            data[t].x * inv + hidden[(size_t)t * DIM + d];
}

// ---------------------------------------------------------------------------
// Tiled SGEMM: C[M,N] = act(A[M,K] @ W[K,N] + bias) (+ add)
// BM=BN=128, BK=16, 256 threads, 8x8 per thread. M,N,K divisible by tiles.
// ACT: 0 = none, 1 = silu
// ---------------------------------------------------------------------------
template <int ACT, bool HAS_ADD>
__global__ __launch_bounds__(256)
void sgemm(const float* __restrict__ A, const float* __restrict__ W,
           const float* __restrict__ bias, const float* __restrict__ add,
           float* __restrict__ C, int M, int N, int K) {
    __shared__ float As[16][128];
    __shared__ float Bs[16][128];
    const int tid = threadIdx.x;
    const int tx = tid & 15;     // 0..15  -> N micro tile
    const int ty = tid >> 4;     // 0..15  -> M micro tile
    const int bm = blockIdx.y * 128;
    const int bn = blockIdx.x * 128;

    float acc[8][8];
#pragma unroll
    for (int i = 0; i < 8; i++)
#pragma unroll
        for (int j = 0; j < 8; j++) acc[i][j] = 0.0f;

    for (int k0 = 0; k0 < K; k0 += 16) {
        // load A tile (transposed into As[k][m])
#pragma unroll
        for (int s = 0; s < 2; s++) {
            int idx = tid + s * 256;          // 0..511
            int r   = idx >> 2;               // 0..127
            int c4  = idx & 3;                // 0..3
            float4 v = *reinterpret_cast<const float4*>(
                &A[(size_t)(bm + r) * K + k0 + c4 * 4]);
            As[c4 * 4 + 0][r] = v.x;
            As[c4 * 4 + 1][r] = v.y;
            As[c4 * 4 + 2][r] = v.z;
            As[c4 * 4 + 3][r] = v.w;
        }
        // load B tile
#pragma unroll
        for (int s = 0; s < 2; s++) {
            int idx = tid + s * 256;
            int r   = idx >> 5;               // 0..15
            int c4  = idx & 31;               // 0..31
            *reinterpret_cast<float4*>(&Bs[r][c4 * 4]) =
                *reinterpret_cast<const float4*>(
                    &W[(size_t)(k0 + r) * N + bn + c4 * 4]);
        }
        __syncthreads();
#pragma unroll
        for (int kk = 0; kk < 16; kk++) {
            float ra[8], rb[8];
            *reinterpret_cast<float4*>(ra)     = *reinterpret_cast<float4*>(&As[kk][ty * 8]);
            *reinterpret_cast<float4*>(ra + 4) = *reinterpret_cast<float4*>(&As[kk][ty * 8 + 4]);
            *reinterpret_cast<float4*>(rb)     = *reinterpret_cast<float4*>(&Bs[kk][tx * 8]);
            *reinterpret_cast<float4*>(rb + 4) = *reinterpret_cast<float4*>(&Bs[kk][tx * 8 + 4]);
#pragma unroll
            for (int i = 0; i < 8; i++)
#pragma unroll
                for (int j = 0; j < 8; j++) acc[i][j] += ra[i] * rb[j];
        }
        __syncthreads();
    }

    // epilogue
#pragma unroll
    for (int i = 0; i < 8; i++) {
        const int r = bm + ty * 8 + i;
#pragma unroll
        for (int j = 0; j < 8; j++) {
            const int c = bn + tx * 8 + j;
            float v = acc[i][j] + bias[c];
            if (ACT == 1) v = v / (1.0f + expf(-v));   // silu
            if (HAS_ADD) v += add[(size_t)r * N + c];
            C[(size_t)r * N + c] = v;
        }
    }
}

// ---------------------------------------------------------------------------
// Launch
// ---------------------------------------------------------------------------
extern "C" void kernel_launch(void* const* d_in, const int* in_sizes, int n_in,
                              void* d_out, int out_size) {
    const float* z      = (const float*)d_in[0];
    const float* pos    = (const float*)d_in[1];
    const float* a      = (const float*)d_in[2];
    const float* hidden = (const float*)d_in[3];
    const float* ln_g   = (const float*)d_in[4];
    const float* ln_b   = (const float*)d_in[5];
    const float* wp1    = (const float*)d_in[6];
    const float* bp1    = (const float*)d_in[7];
    const float* wp2    = (const float*)d_in[8];
    const float* bp2    = (const float*)d_in[9];
    const float* w1     = (const float*)d_in[10];
    const float* b1     = (const float*)d_in[11];
    const float* w2     = (const float*)d_in[12];
    const float* b2     = (const float*)d_in[13];
    float* out = (float*)d_out;

    float *lnz, *hfilt, *znew, *X, *H;
    float2* wfh;
    cudaGetSymbolAddress((void**)&lnz,   g_lnz);
    cudaGetSymbolAddress((void**)&hfilt, g_hfilt);
    cudaGetSymbolAddress((void**)&wfh,   g_wfh);
    cudaGetSymbolAddress((void**)&znew,  g_znew);
    cudaGetSymbolAddress((void**)&X,     g_X);
    cudaGetSymbolAddress((void**)&H,     g_H);

    // 1) filter FFN on positional encodings: h = ffn(pos)
    sgemm<1, false><<<dim3(DFF / 128, LEN / 128), 256>>>(
        pos, wp1, bp1, nullptr, H, LEN, DFF, DIM);
    sgemm<0, false><<<dim3(DIM / 128, LEN / 128), 256>>>(
        H, wp2, bp2, nullptr, hfilt, LEN, DIM, DFF);

    // 2) filter spectrum: WFH[d] = FFT(window * h[:,d], 4096)
    filter_fft<<<DIM, 256>>>(hfilt, a, wfh);

    // 3) LN(z)
    layernorm_rows<<<BATCH * LEN, 256>>>(z, ln_g, ln_b, lnz);

    // 4) FFT convolution per (b, d) column + hidden residual
    fftconv<<<BATCH * DIM, 256>>>(lnz, wfh, hidden, znew);

    // 5) LN(znew)
    layernorm_rows<<<BATCH * LEN, 256>>>(znew, ln_g, ln_b, X);

    // 6) main FFN + residual: out = ffn(X) + znew
    sgemm<1, false><<<dim3(DFF / 128, (BATCH * LEN) / 128), 256>>>(
        X, w1, b1, nullptr, H, BATCH * LEN, DFF, DIM);
    sgemm<0, true><<<dim3(DIM / 128, (BATCH * LEN) / 128), 256>>>(
        H, w2, b2, znew, out, BATCH * LEN, DIM, DFF);
}